// round 5
// baseline (speedup 1.0000x reference)
#include <cuda_runtime.h>
#include <cuda_bf16.h>
#include <stdint.h>

#define NB   8
#define NC   19
#define HW   262144            // 512*512
#define NPIX (NB * HW)         // 2,097,152
#define NPIX4 (NPIX / 4)
#define OHEM_THRESH 0.7f
#define MIN_KEPT_DEFAULT 131072
#define SENTINEL_KEY 0xFFFFFFFFu

// ---------------- device scratch ----------------
__device__ unsigned int g_key[NPIX];      // order-key of logp per pixel (sentinel for invalid)
__device__ unsigned int g_hist1[65536];   // key bits [31:16]
__device__ unsigned int g_hist2[65536];   // key bits [15:0]
__device__ unsigned int g_bin1;
__device__ unsigned int g_rank2;
__device__ unsigned int g_thkey;
__device__ double       g_sum;
__device__ int          g_cnt;

// monotone bit transform: float value order -> unsigned order
__device__ __forceinline__ unsigned orderkey(unsigned b) {
    return b ^ ((b & 0x80000000u) ? 0xFFFFFFFFu : 0x80000000u);
}
// inverse
__device__ __forceinline__ float key_to_float(unsigned k) {
    unsigned b = (k & 0x80000000u) ? (k ^ 0x80000000u) : ~k;
    return __uint_as_float(b);
}

// ---------------- kernel 0: zero scratch ----------------
__global__ void k_zero() {
    int i = blockIdx.x * blockDim.x + threadIdx.x;   // 65536 threads
    g_hist1[i] = 0u;
    g_hist2[i] = 0u;
    if (i == 0) {
        g_sum = 0.0; g_cnt = 0;
        g_bin1 = 0u; g_rank2 = 0u;
        g_thkey = orderkey(__float_as_uint(logf(OHEM_THRESH)));
    }
}

// ---------------- kernel 1: fused softmax-gather -> keys + level-1 histogram ----------
// 4 pixels per thread, float4 loads, 19 independent streams per thread.
__global__ void __launch_bounds__(256) k_pass1(const float* __restrict__ pred,
                                               const int*   __restrict__ tgt) {
    int tid = blockIdx.x * blockDim.x + threadIdx.x;     // 0 .. NPIX4-1
    int q   = tid << 2;                                  // base pixel, 4-aligned
    int n   = q >> 18;
    int hw  = q & (HW - 1);
    const float4* base = (const float4*)(pred + (size_t)n * (NC * HW) + hw);

    int4 t4 = ((const int4*)tgt)[tid];

    float4 s  = make_float4(0.f, 0.f, 0.f, 0.f);
    float4 xt = make_float4(0.f, 0.f, 0.f, 0.f);

#pragma unroll
    for (int c = 0; c < NC; c++) {
        float4 v = __ldg(base + c * (HW / 4));
        s.x += __expf(v.x); s.y += __expf(v.y);
        s.z += __expf(v.z); s.w += __expf(v.w);
        if (c == t4.x) xt.x = v.x;
        if (c == t4.y) xt.y = v.y;
        if (c == t4.z) xt.z = v.z;
        if (c == t4.w) xt.w = v.w;
    }

    // logp = x_t - log(sum exp)  (no max-subtraction: |logits| small, safe in fp32)
    float lp0 = xt.x - __logf(s.x);
    float lp1 = xt.y - __logf(s.y);
    float lp2 = xt.z - __logf(s.z);
    float lp3 = xt.w - __logf(s.w);

    uint4 k;
    k.x = (t4.x != -1) ? orderkey(__float_as_uint(lp0)) : SENTINEL_KEY;
    k.y = (t4.y != -1) ? orderkey(__float_as_uint(lp1)) : SENTINEL_KEY;
    k.z = (t4.z != -1) ? orderkey(__float_as_uint(lp2)) : SENTINEL_KEY;
    k.w = (t4.w != -1) ? orderkey(__float_as_uint(lp3)) : SENTINEL_KEY;

    ((uint4*)g_key)[tid] = k;

    if (k.x != SENTINEL_KEY) atomicAdd(&g_hist1[k.x >> 16], 1u);
    if (k.y != SENTINEL_KEY) atomicAdd(&g_hist1[k.y >> 16], 1u);
    if (k.z != SENTINEL_KEY) atomicAdd(&g_hist1[k.z >> 16], 1u);
    if (k.w != SENTINEL_KEY) atomicAdd(&g_hist1[k.w >> 16], 1u);
}

// ---------------- kernel 2: scan level-1, find winning bin + residual rank ----------
__global__ void k_scan1(const int* __restrict__ min_kept_ptr) {
    __shared__ unsigned s[1024];
    int tid = threadIdx.x;

    unsigned local = 0;
#pragma unroll 8
    for (int i = 0; i < 64; i++) local += g_hist1[(tid << 6) + i];

    s[tid] = local;
    __syncthreads();
    for (int off = 1; off < 1024; off <<= 1) {
        unsigned v = (tid >= off) ? s[tid - off] : 0u;
        __syncthreads();
        s[tid] += v;
        __syncthreads();
    }
    unsigned incl = s[tid];
    unsigned excl = incl - local;
    unsigned total = s[1023];

    if ((int)total <= 0) {
        if (tid == 0) g_bin1 = 0xFFFFFFFFu;   // no valid pixels; thkey stays at 0.7 cut
        return;
    }

    int mk  = min_kept_ptr ? *min_kept_ptr : MIN_KEPT_DEFAULT;
    int idx = min(mk, (int)total - 1);
    if (idx < 0) idx = 0;
    unsigned r = (unsigned)idx;

    if (r >= excl && r < incl) {
        unsigned c = excl;
        for (int i = 0; i < 64; i++) {
            unsigned h = g_hist1[(tid << 6) + i];
            if (r < c + h) { g_bin1 = (unsigned)((tid << 6) + i); g_rank2 = r - c; break; }
            c += h;
        }
    }
}

// ---------------- kernel 3: level-2 histogram over winning bin (pure int streaming) ----
__global__ void __launch_bounds__(256) k_hist2() {
    int tid = blockIdx.x * blockDim.x + threadIdx.x;     // NPIX4 threads
    unsigned b1 = g_bin1;
    uint4 k = ((const uint4*)g_key)[tid];
    if ((k.x >> 16) == b1) atomicAdd(&g_hist2[k.x & 0xFFFFu], 1u);
    if ((k.y >> 16) == b1) atomicAdd(&g_hist2[k.y & 0xFFFFu], 1u);
    if ((k.z >> 16) == b1) atomicAdd(&g_hist2[k.z & 0xFFFFu], 1u);
    if ((k.w >> 16) == b1) atomicAdd(&g_hist2[k.w & 0xFFFFu], 1u);
}

// ---------------- kernel 4: scan level-2, reconstruct exact kth key, final threshold ----
__global__ void k_scan2() {
    __shared__ unsigned s[1024];
    int tid = threadIdx.x;
    unsigned b1 = g_bin1;
    if (b1 == 0xFFFFFFFFu) return;

    unsigned local = 0;
#pragma unroll 8
    for (int i = 0; i < 64; i++) local += g_hist2[(tid << 6) + i];

    s[tid] = local;
    __syncthreads();
    for (int off = 1; off < 1024; off <<= 1) {
        unsigned v = (tid >= off) ? s[tid - off] : 0u;
        __syncthreads();
        s[tid] += v;
        __syncthreads();
    }
    unsigned incl = s[tid];
    unsigned excl = incl - local;
    unsigned r = g_rank2;

    if (r >= excl && r < incl) {
        unsigned c = excl;
        for (int i = 0; i < 64; i++) {
            unsigned h = g_hist2[(tid << 6) + i];
            if (r < c + h) {
                unsigned kth = (b1 << 16) | (unsigned)((tid << 6) + i);
                unsigned k07 = orderkey(__float_as_uint(logf(OHEM_THRESH)));
                g_thkey = max(kth, k07);
                break;
            }
            c += h;
        }
    }
}

// ---------------- kernel 5: masked sum + count (pure ALU, no MUFU) ----------------
__global__ void __launch_bounds__(256) k_reduce() {
    unsigned th = g_thkey;
    int tid = blockIdx.x * blockDim.x + threadIdx.x;     // NPIX4 threads
    uint4 k = ((const uint4*)g_key)[tid];

    float acc = 0.0f;
    int   cnt = 0;
    if (k.x < th) { acc += -key_to_float(k.x); cnt++; }
    if (k.y < th) { acc += -key_to_float(k.y); cnt++; }
    if (k.z < th) { acc += -key_to_float(k.z); cnt++; }
    if (k.w < th) { acc += -key_to_float(k.w); cnt++; }

    double d = (double)acc;
    for (int off = 16; off > 0; off >>= 1) {
        d   += __shfl_down_sync(0xFFFFFFFFu, d, off);
        cnt += __shfl_down_sync(0xFFFFFFFFu, cnt, off);
    }
    __shared__ double s_acc[8];
    __shared__ int    s_cnt[8];
    int lane = threadIdx.x & 31, wid = threadIdx.x >> 5;
    if (lane == 0) { s_acc[wid] = d; s_cnt[wid] = cnt; }
    __syncthreads();
    if (wid == 0) {
        d   = (lane < 8) ? s_acc[lane] : 0.0;
        cnt = (lane < 8) ? s_cnt[lane] : 0;
        for (int off = 4; off > 0; off >>= 1) {
            d   += __shfl_down_sync(0xFFFFFFFFu, d, off);
            cnt += __shfl_down_sync(0xFFFFFFFFu, cnt, off);
        }
        if (lane == 0) {
            atomicAdd(&g_sum, d);
            atomicAdd(&g_cnt, cnt);
        }
    }
}

// ---------------- kernel 6: finalize ----------------
__global__ void k_final(float* __restrict__ out) {
    int c = g_cnt;
    out[0] = (float)(g_sum / (double)(c > 0 ? c : 1));
}

// ---------------- launch ----------------
extern "C" void kernel_launch(void* const* d_in, const int* in_sizes, int n_in,
                              void* d_out, int out_size) {
    const float* pred = (const float*)d_in[0];
    const int*   tgt  = (const int*)d_in[1];
    const int*   mk   = (n_in >= 3) ? (const int*)d_in[2] : nullptr;
    float*       out  = (float*)d_out;

    k_zero  <<<256, 256>>>();
    k_pass1 <<<NPIX4 / 256, 256>>>(pred, tgt);
    k_scan1 <<<1, 1024>>>(mk);
    k_hist2 <<<NPIX4 / 256, 256>>>();
    k_scan2 <<<1, 1024>>>();
    k_reduce<<<NPIX4 / 256, 256>>>();
    k_final <<<1, 1>>>(out);
}